// round 10
// baseline (speedup 1.0000x reference)
#include <cuda_runtime.h>
#include <cuda_bf16.h>
#include <stdint.h>
#include <math.h>

#define S_LEN 32
#define BB    64
#define H     512
#define H2    1024
#define H4    2048

typedef __nv_bfloat16 bf16;

// ---------------- persistent device state ----------------
__device__ bf16 g_W2h[2][H2 * H];
__device__ bf16 g_Wk [2][H * H4];
__device__ bf16 g_Wr [2][H * H4];
__device__ bf16 g_bSh[2][S_LEN][BB * H];
__device__ bf16 g_bTh[2][S_LEN][BB * H];
__device__ bf16 g_bSx[2][S_LEN][BB * H];
__device__ bf16 g_bTx[2][S_LEN][BB * H];
__device__ bf16 g_bHm[2][S_LEN][BB * H];
__device__ float g_fSm[S_LEN][BB * H];
__device__ float g_fTm[S_LEN][BB * H];
__device__ float g_fSx[S_LEN][BB * H];
__device__ float g_fTx[S_LEN][BB * H];
__device__ float g_fZS[S_LEN][BB * H4];
__device__ float g_fZT[S_LEN][BB * H4];

// grid barrier state
__device__ unsigned g_bar_count = 0;
__device__ volatile unsigned g_bar_gen = 0;

// ---------------- helpers ----------------
__device__ __forceinline__ float sigf(float x) { return 1.0f / (1.0f + __expf(-x)); }
__device__ __forceinline__ float tanh_fast(float x) {
    float e = __expf(2.0f * x);
    return 1.0f - 2.0f / (e + 1.0f);
}
__device__ __forceinline__ void split_store(float v, bf16* phi, bf16* plo) {
    bf16 hi = __float2bfloat16(v);
    bf16 lo = __float2bfloat16(v - __bfloat162float(hi));
    *phi = hi; *plo = lo;
}
__device__ __forceinline__ void cp16(void* smem, const void* g) {
    uint32_t s = (uint32_t)__cvta_generic_to_shared(smem);
    asm volatile("cp.async.cg.shared.global [%0], [%1], 16;\n" :: "r"(s), "l"(g));
}
__device__ __forceinline__ void cp_commit() { asm volatile("cp.async.commit_group;\n"); }
template<int N> __device__ __forceinline__ void cp_wait() {
    asm volatile("cp.async.wait_group %0;\n" :: "n"(N));
}
__device__ __forceinline__ void ldsm_x4(uint32_t& r0, uint32_t& r1, uint32_t& r2, uint32_t& r3, uint32_t addr) {
    asm volatile("ldmatrix.sync.aligned.m8n8.x4.shared.b16 {%0,%1,%2,%3},[%4];\n"
                 : "=r"(r0), "=r"(r1), "=r"(r2), "=r"(r3) : "r"(addr));
}
__device__ __forceinline__ void ldsm_x2t(uint32_t& r0, uint32_t& r1, uint32_t addr) {
    asm volatile("ldmatrix.sync.aligned.m8n8.x2.trans.shared.b16 {%0,%1},[%2];\n"
                 : "=r"(r0), "=r"(r1) : "r"(addr));
}
__device__ __forceinline__ void mma16816(float* d, const uint32_t* a, const uint32_t* b) {
    asm volatile("mma.sync.aligned.m16n8k16.row.col.f32.bf16.bf16.f32 "
                 "{%0,%1,%2,%3},{%4,%5,%6,%7},{%8,%9},{%0,%1,%2,%3};\n"
                 : "+f"(d[0]), "+f"(d[1]), "+f"(d[2]), "+f"(d[3])
                 : "r"(a[0]), "r"(a[1]), "r"(a[2]), "r"(a[3]), "r"(b[0]), "r"(b[1]));
}

__device__ __forceinline__ void grid_barrier() {
    __syncthreads();
    if (threadIdx.x == 0) {
        __threadfence();
        unsigned gen = g_bar_gen;
        if (atomicInc(&g_bar_count, gridDim.x - 1) == gridDim.x - 1) {
            g_bar_gen = gen + 1;
        } else {
            while (g_bar_gen == gen) { __nanosleep(32); }
        }
    }
    __syncthreads();
}

// ---------------- pass-fused GEMM core (256 threads, 8 warps) ----------------
// BM=64, BN=128, BK=32, warp tile 32x32 (2m x 4n), m16n8k16.
// Per K-tile: load A_hi, A_lo, B_hi, B_lo once; passes hi*hi + hi*lo + lo*hi.
// 3-stage cp.async pipeline, one __syncthreads per iteration.
#define SA 40
#define SB 136
#define A_PLANE (64 * SA)                       // 2560 elems
#define B_PLANE (32 * SB)                       // 4352 elems
#define STAGE_ELEMS (2 * A_PLANE + 2 * B_PLANE) // 13824 elems
#define NSTAGE 3
#define SMEM_BYTES (NSTAGE * STAGE_ELEMS * 2)   // 82944 bytes

template<int NIT, bool CONCAT, bool GSTRIDE>
__device__ __forceinline__ void gemm_core(
    bf16* sm,
    const bf16* A_hi0, const bf16* A_lo0,
    const bf16* A_hi1, const bf16* A_lo1,
    const bf16* W_hi, const bf16* W_lo, int ldw,
    int nblk, float acc[2][4][4])
{
    const int tid = threadIdx.x;
    const int lane = tid & 31;
    const int warp = tid >> 5;
    const int warp_m = warp >> 2;
    const int warp_n = warp & 3;

    const int arow = tid >> 2;           // 0..63
    const int acol = (tid & 3) * 8;      // 0,8,16,24
    const int brow0 = tid >> 4;          // 0..15
    const int bcol0 = (tid & 15) * 8;    // 0..120
    const int gcolB = GSTRIDE ? ((bcol0 >> 5) * H + nblk * 32 + (bcol0 & 31))
                              : (nblk * 128 + bcol0);

    auto issue = [&](int it) {
        int kk = it * 32;
        int slot = it % NSTAGE;
        bf16* st = sm + slot * STAGE_ELEMS;
        const bf16 *Ah, *Al;
        if (CONCAT && kk >= H) { Ah = A_hi1 + (kk - H); Al = A_lo1 + (kk - H); }
        else                   { Ah = A_hi0 + kk;       Al = A_lo0 + kk; }
        cp16(st + arow * SA + acol,            Ah + arow * H + acol);
        cp16(st + A_PLANE + arow * SA + acol,  Al + arow * H + acol);
        const bf16* Wh = W_hi + (size_t)kk * ldw + gcolB;
        const bf16* Wl = W_lo + (size_t)kk * ldw + gcolB;
        bf16* Bh = st + 2 * A_PLANE;
        bf16* Bl = Bh + B_PLANE;
        cp16(Bh + brow0 * SB + bcol0,        Wh + brow0 * ldw);
        cp16(Bh + (brow0 + 16) * SB + bcol0, Wh + (brow0 + 16) * ldw);
        cp16(Bl + brow0 * SB + bcol0,        Wl + brow0 * ldw);
        cp16(Bl + (brow0 + 16) * SB + bcol0, Wl + (brow0 + 16) * ldw);
        cp_commit();
    };

    issue(0);
    if (NIT > 1) issue(1);

    const uint32_t base = (uint32_t)__cvta_generic_to_shared(sm);

    for (int it = 0; it < NIT; ++it) {
        if (it < NIT - 1) cp_wait<NSTAGE - 2>();
        else              cp_wait<0>();
        __syncthreads();
        if (it + NSTAGE - 1 < NIT) issue(it + NSTAGE - 1);

        const int slot = it % NSTAGE;
        const uint32_t st  = base + (uint32_t)(slot * STAGE_ELEMS * 2);
        const uint32_t aHi = st;
        const uint32_t aLo = st + A_PLANE * 2;
        const uint32_t bHi = st + 4 * A_PLANE;
        const uint32_t bLo = bHi + B_PLANE * 2;

#pragma unroll
        for (int ks = 0; ks < 2; ks++) {
            uint32_t ah[2][4], al[2][4];
#pragma unroll
            for (int mf = 0; mf < 2; mf++) {
                int row = warp_m * 32 + mf * 16 + (lane & 15);
                int col = ks * 16 + (lane >> 4) * 8;
                uint32_t off = (uint32_t)((row * SA + col) * 2);
                ldsm_x4(ah[mf][0], ah[mf][1], ah[mf][2], ah[mf][3], aHi + off);
                ldsm_x4(al[mf][0], al[mf][1], al[mf][2], al[mf][3], aLo + off);
            }
            uint32_t bh[4][2], bl[4][2];
#pragma unroll
            for (int nf = 0; nf < 4; nf++) {
                int row = ks * 16 + (lane & 15);
                int col = nf * 32 + warp_n * 8;
                uint32_t off = (uint32_t)((row * SB + col) * 2);
                ldsm_x2t(bh[nf][0], bh[nf][1], bHi + off);
                ldsm_x2t(bl[nf][0], bl[nf][1], bLo + off);
            }
#pragma unroll
            for (int mf = 0; mf < 2; mf++)
#pragma unroll
                for (int nf = 0; nf < 4; nf++) {
                    mma16816(acc[mf][nf], ah[mf], bh[nf]);
                    mma16816(acc[mf][nf], ah[mf], bl[nf]);
                    mma16816(acc[mf][nf], al[mf], bh[nf]);
                }
        }
    }
    __syncthreads();   // protect stages before next tile reuses them
}

// ---------------- setup kernels ----------------
__global__ void prep_weights(const float* __restrict__ W_H2h,
                             const float* __restrict__ Wk,
                             const float* __restrict__ Wr) {
    int idx = blockIdx.x * blockDim.x + threadIdx.x;
    if (idx < H2 * H) {
        split_store(W_H2h[idx], &g_W2h[0][idx], &g_W2h[1][idx]);
    }
    if (idx < H * H4) {
        split_store(Wk[idx], &g_Wk[0][idx], &g_Wk[1][idx]);
        split_store(Wr[idx], &g_Wr[0][idx], &g_Wr[1][idx]);
    }
}

__global__ void init_state(const float* __restrict__ src, const float* __restrict__ tgt) {
    int idx = blockIdx.x * blockDim.x + threadIdx.x;
    const int n = S_LEN * BB * H;
    if (idx >= n) return;
    float s = src[idx], t = tgt[idx];
    ((float*)g_fSx)[idx] = s;
    ((float*)g_fTx)[idx] = t;
    ((float*)g_fSm)[idx] = 0.0f;
    ((float*)g_fTm)[idx] = 0.0f;
    split_store(s, &((bf16*)g_bSx[0])[idx], &((bf16*)g_bSx[1])[idx]);
    split_store(t, &((bf16*)g_bTx[0])[idx], &((bf16*)g_bTx[1])[idx]);
    bf16 z = __float2bfloat16(0.0f);
    ((bf16*)g_bSh[0])[idx] = z; ((bf16*)g_bSh[1])[idx] = z;
    ((bf16*)g_bTh[0])[idx] = z; ((bf16*)g_bTh[1])[idx] = z;
}

// ---------------- persistent grid kernel: all 63 waves ----------------
__global__ __launch_bounds__(256, 2) void grid_kernel(const float* __restrict__ b_H2h,
                                                      const float* __restrict__ b_lstm,
                                                      float* __restrict__ out) {
    extern __shared__ __align__(16) bf16 sm[];
    const int tid = threadIdx.x;
    const int lane = tid & 31;
    const int warp = tid >> 5;
    const int warp_m = warp >> 2;
    const int warp_n = warp & 3;
    const int r0 = warp_m * 32 + (lane >> 2);
    const int c0 = warp_n * 8 + (lane & 3) * 2;

    for (int d = 0; d < 63; d++) {
        const int lo = (d - 31 > 0) ? d - 31 : 0;
        const int hic = (d < 31) ? d : 31;
        const int nc = hic - lo + 1;

        // ---------------- phase A ----------------
        const int nwA = 36 * nc;
        for (int w = blockIdx.x; w < nwA; w += gridDim.x) {
            const int c = w / 36;
            const int t = w - c * 36;
            const int i = lo + c;
            const int j = d - i;

            float acc[2][4][4];
#pragma unroll
            for (int a = 0; a < 2; a++)
#pragma unroll
                for (int b = 0; b < 4; b++)
#pragma unroll
                    for (int cc = 0; cc < 4; cc++) acc[a][b][cc] = 0.0f;

            if (t < 4) {
                gemm_core<32, true, false>(sm,
                    g_bSh[0][i], g_bSh[1][i], g_bTh[0][j], g_bTh[1][j],
                    g_W2h[0], g_W2h[1], H, t, acc);
#pragma unroll
                for (int mf = 0; mf < 2; mf++)
#pragma unroll
                    for (int nf = 0; nf < 4; nf++)
#pragma unroll
                        for (int rr = 0; rr < 2; rr++)
#pragma unroll
                            for (int cc = 0; cc < 2; cc++) {
                                int m = r0 + mf * 16 + rr * 8;
                                int n = t * 128 + nf * 32 + c0 + cc;
                                float v = acc[mf][nf][rr * 2 + cc] + b_H2h[n];
                                split_store(v, &g_bHm[0][i][m * H + n], &g_bHm[1][i][m * H + n]);
                            }
            } else if (t < 20) {
                int nblk = t - 4;
                gemm_core<16, false, false>(sm,
                    g_bSx[0][i], g_bSx[1][i], nullptr, nullptr,
                    g_Wk[0], g_Wk[1], H4, nblk, acc);
#pragma unroll
                for (int mf = 0; mf < 2; mf++)
#pragma unroll
                    for (int nf = 0; nf < 4; nf++)
#pragma unroll
                        for (int rr = 0; rr < 2; rr++)
#pragma unroll
                            for (int cc = 0; cc < 2; cc++) {
                                int m = r0 + mf * 16 + rr * 8;
                                int n = nblk * 128 + nf * 32 + c0 + cc;
                                g_fZS[i][m * H4 + n] = acc[mf][nf][rr * 2 + cc];
                            }
            } else {
                int nblk = t - 20;
                gemm_core<16, false, false>(sm,
                    g_bTx[0][j], g_bTx[1][j], nullptr, nullptr,
                    g_Wk[0], g_Wk[1], H4, nblk, acc);
#pragma unroll
                for (int mf = 0; mf < 2; mf++)
#pragma unroll
                    for (int nf = 0; nf < 4; nf++)
#pragma unroll
                        for (int rr = 0; rr < 2; rr++)
#pragma unroll
                            for (int cc = 0; cc < 2; cc++) {
                                int m = r0 + mf * 16 + rr * 8;
                                int n = nblk * 128 + nf * 32 + c0 + cc;
                                g_fZT[j][m * H4 + n] = acc[mf][nf][rr * 2 + cc];
                            }
            }
        }
        grid_barrier();

        // ---------------- phase B ----------------
        const int nwB = 16 * nc;
        for (int w = blockIdx.x; w < nwB; w += gridDim.x) {
            const int c = w >> 4;
            const int nblk = w & 15;
            const int i = lo + c;
            const int j = d - i;

            float acc[2][4][4];   // [mf][gate][frag]
#pragma unroll
            for (int a = 0; a < 2; a++)
#pragma unroll
                for (int b = 0; b < 4; b++)
#pragma unroll
                    for (int cc = 0; cc < 4; cc++) acc[a][b][cc] = 0.0f;

            gemm_core<16, false, true>(sm,
                g_bHm[0][i], g_bHm[1][i], nullptr, nullptr,
                g_Wr[0], g_Wr[1], H4, nblk, acc);

#pragma unroll
            for (int mf = 0; mf < 2; mf++)
#pragma unroll
                for (int rr = 0; rr < 2; rr++)
#pragma unroll
                    for (int cc = 0; cc < 2; cc++) {
                        const int m = r0 + mf * 16 + rr * 8;
                        const int nn = nblk * 32 + c0 + cc;
                        const int ridx = rr * 2 + cc;
                        const float ri = acc[mf][0][ridx];
                        const float rf = acc[mf][1][ridx];
                        const float rg = acc[mf][2][ridx];
                        const float ro = acc[mf][3][ridx];
                        const float bi = b_lstm[nn];
                        const float bfv = b_lstm[H + nn];
                        const float bg = b_lstm[2 * H + nn];
                        const float bo = b_lstm[3 * H + nn];
                        {
                            float zi = ri + __ldcg(&g_fZS[i][m * H4 + nn])         + bi;
                            float zf = rf + __ldcg(&g_fZS[i][m * H4 + H + nn])     + bfv;
                            float zg = rg + __ldcg(&g_fZS[i][m * H4 + 2 * H + nn]) + bg;
                            float zo = ro + __ldcg(&g_fZS[i][m * H4 + 3 * H + nn]) + bo;
                            float c2 = sigf(zf) * __ldcg(&g_fSm[i][m * H + nn]) + sigf(zi) * tanh_fast(zg);
                            float h2 = sigf(zo) * tanh_fast(c2);
                            g_fSm[i][m * H + nn] = c2;
                            g_fSx[i][m * H + nn] = h2;
                            bf16 hib = __float2bfloat16(h2);
                            bf16 lob = __float2bfloat16(h2 - __bfloat162float(hib));
                            g_bSx[0][i][m * H + nn] = hib; g_bSx[1][i][m * H + nn] = lob;
                            g_bSh[0][i][m * H + nn] = hib; g_bSh[1][i][m * H + nn] = lob;
                        }
                        {
                            float zi = ri + __ldcg(&g_fZT[j][m * H4 + nn])         + bi;
                            float zf = rf + __ldcg(&g_fZT[j][m * H4 + H + nn])     + bfv;
                            float zg = rg + __ldcg(&g_fZT[j][m * H4 + 2 * H + nn]) + bg;
                            float zo = ro + __ldcg(&g_fZT[j][m * H4 + 3 * H + nn]) + bo;
                            float c2 = sigf(zf) * __ldcg(&g_fTm[j][m * H + nn]) + sigf(zi) * tanh_fast(zg);
                            float h2 = sigf(zo) * tanh_fast(c2);
                            g_fTm[j][m * H + nn] = c2;
                            g_fTx[j][m * H + nn] = h2;
                            bf16 hib = __float2bfloat16(h2);
                            bf16 lob = __float2bfloat16(h2 - __bfloat162float(hib));
                            g_bTx[0][j][m * H + nn] = hib; g_bTx[1][j][m * H + nn] = lob;
                            g_bTh[0][j][m * H + nn] = hib; g_bTh[1][j][m * H + nn] = lob;
                        }
                    }
        }
        grid_barrier();
    }

    // ---------------- output ----------------
    const int n = S_LEN * BB * H;
    for (int idx = blockIdx.x * blockDim.x + tid; idx < n; idx += gridDim.x * blockDim.x) {
        out[idx]     = __ldcg(&((float*)g_fSx)[idx]);
        out[n + idx] = __ldcg(&((float*)g_fTx)[idx]);
    }
}

extern "C" void kernel_launch(void* const* d_in, const int* in_sizes, int n_in,
                              void* d_out, int out_size) {
    const float* source = (const float*)d_in[0];
    const float* target = (const float*)d_in[1];
    const float* W_H2h  = (const float*)d_in[2];
    const float* b_H2h  = (const float*)d_in[3];
    const float* Wk     = (const float*)d_in[4];
    const float* Wr     = (const float*)d_in[5];
    const float* b_lstm = (const float*)d_in[6];
    float* out = (float*)d_out;

    static int nsm = 0;
    if (nsm == 0) {
        cudaDeviceGetAttribute(&nsm, cudaDevAttrMultiProcessorCount, 0);
        cudaFuncSetAttribute(grid_kernel, cudaFuncAttributeMaxDynamicSharedMemorySize, SMEM_BYTES);
    }

    const int N = S_LEN * BB * H;
    prep_weights<<<(H * H4 + 255) / 256, 256>>>(W_H2h, Wk, Wr);
    init_state<<<(N + 255) / 256, 256>>>(source, target);
    grid_kernel<<<2 * nsm, 256, SMEM_BYTES>>>(b_H2h, b_lstm, out);
}